// round 3
// baseline (speedup 1.0000x reference)
#include <cuda_runtime.h>
#include <math.h>

#define BB 8
#define TT 64
#define NN 256
#define HH 256
#define DI 6
#define DO 9
#define G3 768
#define NBLK 128

typedef unsigned long long u64;

// ---------------- scratch ----------------
__device__ __align__(16) float g_gx[(size_t)BB*TT*NN*G3];
__device__ __align__(16) float g_hseq[(size_t)BB*TT*NN*HH];
__device__ __align__(16) float g_Axseq[(size_t)BB*TT*NN*HH];
__device__ __align__(16) float g_h [BB*NN*HH];
__device__ __align__(16) float g_Ah[BB*NN*HH];
__device__ __align__(16) float g_Au[BB*NN*HH];
__device__ __align__(16) float g_pzr[(size_t)BB*NN*512];     // full gzr pre-activation (GEMM part)
__device__ __align__(16) float g_pc [(size_t)2*BB*NN*HH];    // c GEMM K-split(2) partials
__device__ int   g_cnt[NN];
__device__ int   g_col[NN*NN];
__device__ float g_val[NN*NN];

__device__ unsigned g_barcnt;
__device__ volatile unsigned g_bargen;

// ---------------- helpers ----------------
union F4U { float4 f; u64 u[2]; };

__device__ __forceinline__ void ffma2(u64& d, u64 a, u64 b){
    asm("fma.rn.f32x2 %0, %1, %2, %0;" : "+l"(d) : "l"(a), "l"(b));
}
__device__ __forceinline__ float2 unpack2(u64 v){
    float2 f; asm("mov.b64 {%0, %1}, %2;" : "=f"(f.x), "=f"(f.y) : "l"(v)); return f;
}
__device__ __forceinline__ float sigmoidf_(float x){ return 1.0f / (1.0f + __expf(-x)); }

__device__ __forceinline__ void gridbar(unsigned* gen){
    __syncthreads();
    if (threadIdx.x == 0){
        unsigned target = *gen + 1;
        __threadfence();
        if (atomicAdd(&g_barcnt, 1u) == NBLK - 1){
            g_barcnt = 0;
            __threadfence();
            g_bargen = target;
        } else {
            while (g_bargen != target) { }
        }
        *gen = target;
    }
    __syncthreads();
}

// ---------------- CSR build ----------------
__global__ void build_csr(const float* __restrict__ adj){
    int n = threadIdx.x;
    int c = 0;
    for (int m = 0; m < NN; m++){
        float v = adj[n*NN + m];
        if (v != 0.0f){ g_col[n*NN + c] = m; g_val[n*NN + c] = v; c++; }
    }
    g_cnt[n] = c;
}

// ---------------- layer-0 gx ----------------
__global__ void prep_gx0(const float* __restrict__ x2d, const float* __restrict__ mask,
                         const float* __restrict__ Wx0, const float* __restrict__ b0){
    __shared__ float xm[NN*DI];
    __shared__ float ax[NN*DI];
    __shared__ float Ws[DI*G3];
    int bt = blockIdx.x;
    int tid = threadIdx.x;

    for (int i = tid; i < NN*DI; i += 256){
        int n = i / DI;
        xm[i] = x2d[(size_t)bt*NN*DI + i] * mask[(size_t)bt*NN + n];
    }
    for (int i = tid; i < DI*G3; i += 256) Ws[i] = Wx0[i];
    __syncthreads();

    {
        int n = tid;
        float a0=0,a1=0,a2=0,a3=0,a4=0,a5=0;
        int cn = g_cnt[n];
        for (int e = 0; e < cn; e++){
            int m = g_col[n*NN + e];
            float w = g_val[n*NN + e];
            const float* xr = xm + m*DI;
            a0 += w*xr[0]; a1 += w*xr[1]; a2 += w*xr[2];
            a3 += w*xr[3]; a4 += w*xr[4]; a5 += w*xr[5];
        }
        float* ar = ax + n*DI;
        ar[0]=a0; ar[1]=a1; ar[2]=a2; ar[3]=a3; ar[4]=a4; ar[5]=a5;
    }
    __syncthreads();

    for (int jj = 0; jj < 3; jj++){
        int j = tid + (jj << 8);
        float w0=Ws[j], w1=Ws[G3+j], w2=Ws[2*G3+j], w3=Ws[3*G3+j], w4=Ws[4*G3+j], w5=Ws[5*G3+j];
        float bj = b0[j];
        float* gout = g_gx + (size_t)bt*NN*G3 + j;
        for (int n = 0; n < NN; n++){
            const float* axr = ax + n*DI;
            float s = bj + axr[0]*w0 + axr[1]*w1 + axr[2]*w2
                         + axr[3]*w3 + axr[4]*w4 + axr[5]*w5;
            gout[(size_t)n*G3] = s;
        }
    }
}

// ---------------- 128x64 f32x2 GEMM tile, prefetch, no-mov inner loop ----------------
// A rows via __ldcg (fresh cross-CTA data); B via __ldg (weights, L1-resident).
template<int KLEN>
__device__ __forceinline__ void gemm_tile64(const float* __restrict__ Ap, int lda,
                                            const float* __restrict__ Bp, int ldb,
                                            float* __restrict__ Cp, int ldc,
                                            float* sA, float* sB)
{
    int tid = threadIdx.x;
    int lrow = tid >> 1, lk = (tid & 1) << 3;   // A stage: row, k-offset
    int bk = tid >> 4, bc = (tid & 15) << 2;    // B stage: k-row, 4 cols
    int ty = tid >> 4, tx = tid & 15;           // compute: rows ty*8, cols tx*4

    u64 acc[4][4];
    #pragma unroll
    for (int i = 0; i < 4; i++)
        #pragma unroll
        for (int j = 0; j < 4; j++) acc[i][j] = 0ull;

    const float* ag = Ap + (size_t)lrow*lda + lk;
    const float* bg = Bp + (size_t)bk*ldb + bc;

    float4 a0 = __ldcg((const float4*)ag);
    float4 a1 = __ldcg((const float4*)(ag + 4));
    float4 b0 = __ldg((const float4*)bg);

    #pragma unroll 2
    for (int kc = 0; kc < KLEN; kc += 16){
        sA[(lk+0)*128 + lrow] = a0.x; sA[(lk+1)*128 + lrow] = a0.y;
        sA[(lk+2)*128 + lrow] = a0.z; sA[(lk+3)*128 + lrow] = a0.w;
        sA[(lk+4)*128 + lrow] = a1.x; sA[(lk+5)*128 + lrow] = a1.y;
        sA[(lk+6)*128 + lrow] = a1.z; sA[(lk+7)*128 + lrow] = a1.w;
        float* sbp = sB + bk*128 + bc*2;
        ((float4*)sbp)[0] = make_float4(b0.x, b0.x, b0.y, b0.y);
        ((float4*)sbp)[1] = make_float4(b0.z, b0.z, b0.w, b0.w);
        __syncthreads();
        if (kc + 16 < KLEN){
            a0 = __ldcg((const float4*)(ag + kc + 16));
            a1 = __ldcg((const float4*)(ag + kc + 20));
            b0 = __ldg((const float4*)(bg + (size_t)(kc + 16)*ldb));
        }
        #pragma unroll
        for (int p = 0; p < 16; p++){
            F4U ta0, ta1, tb0, tb1;
            ta0.f = *(const float4*)(sA + p*128 + ty*8);
            ta1.f = *(const float4*)(sA + p*128 + ty*8 + 4);
            tb0.f = *(const float4*)(sB + p*128 + tx*8);
            tb1.f = *(const float4*)(sB + p*128 + tx*8 + 4);
            u64 ar[4] = { ta0.u[0], ta0.u[1], ta1.u[0], ta1.u[1] };
            u64 bd[4] = { tb0.u[0], tb0.u[1], tb1.u[0], tb1.u[1] };
            #pragma unroll
            for (int i = 0; i < 4; i++)
                #pragma unroll
                for (int j = 0; j < 4; j++) ffma2(acc[i][j], ar[i], bd[j]);
        }
        __syncthreads();
    }

    #pragma unroll
    for (int i = 0; i < 4; i++){
        float2 c0 = unpack2(acc[i][0]);
        float2 c1 = unpack2(acc[i][1]);
        float2 c2 = unpack2(acc[i][2]);
        float2 c3 = unpack2(acc[i][3]);
        float* rp = Cp + (size_t)(ty*8 + 2*i)*ldc + tx*4;
        *(float4*)rp         = make_float4(c0.x, c1.x, c2.x, c3.x);
        *(float4*)(rp + ldc) = make_float4(c0.y, c1.y, c2.y, c3.y);
    }
}

// ---------------- smem spconv: 16-col slice, optional dual output ----------------
__device__ __forceinline__ void spconv16(const float* su, float* dst1, float* dst2){
    int n = threadIdx.x;
    float4 a0 = make_float4(0,0,0,0), a1 = a0, a2 = a0, a3 = a0;
    int cn = g_cnt[n];
    const int*   cp = g_col + n*NN;
    const float* vp = g_val + n*NN;
    for (int e = 0; e < cn; e++){
        int m = cp[e]; float w = vp[e];
        const float4* sm = (const float4*)(su + m*20);
        float4 s0 = sm[0], s1 = sm[1], s2 = sm[2], s3 = sm[3];
        a0.x += w*s0.x; a0.y += w*s0.y; a0.z += w*s0.z; a0.w += w*s0.w;
        a1.x += w*s1.x; a1.y += w*s1.y; a1.z += w*s1.z; a1.w += w*s1.w;
        a2.x += w*s2.x; a2.y += w*s2.y; a2.z += w*s2.z; a2.w += w*s2.w;
        a3.x += w*s3.x; a3.y += w*s3.y; a3.z += w*s3.z; a3.w += w*s3.w;
    }
    float4* d1 = (float4*)(dst1 + (size_t)n*HH);
    d1[0] = a0; d1[1] = a1; d1[2] = a2; d1[3] = a3;
    if (dst2){
        float4* d2 = (float4*)(dst2 + (size_t)n*HH);
        d2[0] = a0; d2[1] = a1; d2[2] = a2; d2[3] = a3;
    }
}

// ---------------- persistent per-layer recurrence ----------------
__global__ void __launch_bounds__(256, 1) gcgru_layer(const float* __restrict__ Wh, int writeAx){
    __shared__ __align__(16) float SBUF[5184];
    float* sA = SBUF;
    float* sB = SBUF + 2048;
    int tid = threadIdx.x;
    int bid = blockIdx.x;
    unsigned gen = g_bargen;

    {   // zero h and Ah
        float4 z4 = make_float4(0,0,0,0);
        float4* h4 = (float4*)g_h;
        float4* a4 = (float4*)g_Ah;
        for (int i = bid*256 + tid; i < BB*NN*HH/4; i += NBLK*256){ h4[i] = z4; a4[i] = z4; }
    }
    gridbar(&gen);

    int q   = bid >> 4;
    int j2b = (bid & 15) << 4;

    for (int t = 0; t < TT; t++){
        // ---- P1: gzr-GEMM: g_pzr = Ah @ Wh[:, :512]  (16 r-tiles x 8 j-tiles) ----
        {
            int r0 = (bid >> 3) << 7;
            int j0 = (bid & 7) << 6;
            gemm_tile64<256>(g_Ah + (size_t)r0*HH, HH,
                             Wh + j0, G3,
                             g_pzr + (size_t)r0*512 + j0, 512, sA, sB);
        }
        gridbar(&gen);
        // ---- P2: r = sig(pzr_r + gx_r); u = r*h; Au = A (x) u ----
        {
            float* su = SBUF;
            int n = tid, row = (q << 8) + n;
            size_t rowt = ((size_t)((q << 6) + t))*256 + n;
            const float4* pz = (const float4*)(g_pzr + (size_t)row*512 + 256 + j2b);
            const float4* gz = (const float4*)(g_gx + rowt*G3 + 256 + j2b);
            const float4* hz = (const float4*)(g_h + (size_t)row*HH + j2b);
            float4* sun = (float4*)(su + n*20);
            #pragma unroll
            for (int w = 0; w < 4; w++){
                float4 p = __ldcg(pz + w);
                float4 g = __ldg(gz + w);
                float4 h4 = __ldcg(hz + w);
                float4 u;
                u.x = sigmoidf_(p.x + g.x) * h4.x;
                u.y = sigmoidf_(p.y + g.y) * h4.y;
                u.z = sigmoidf_(p.z + g.z) * h4.z;
                u.w = sigmoidf_(p.w + g.w) * h4.w;
                sun[w] = u;
            }
            __syncthreads();
            spconv16(su, g_Au + (size_t)(q << 8)*HH + j2b, (float*)0);
        }
        gridbar(&gen);
        // ---- P3: c-GEMM partials: g_pc[ks] = Au[:,k0:] @ Wh[k0:, 512:]  (32 tiles x ks2) ----
        {
            int ks = bid >> 6, tt2 = bid & 63;
            int r0 = (tt2 >> 2) << 7;
            int j0 = (tt2 & 3) << 6;
            int k0 = ks << 7;
            gemm_tile64<128>(g_Au + (size_t)r0*HH + k0, HH,
                             Wh + (size_t)k0*G3 + 512 + j0, G3,
                             g_pc + (size_t)ks*(BB*NN*HH) + (size_t)r0*HH + j0, HH, sA, sB);
        }
        gridbar(&gen);
        // ---- P4: z, c, h update; hseq write; Ah = A (x) h (and Axseq for layer 0) ----
        {
            float* sh = SBUF;
            int n = tid, row = (q << 8) + n;
            size_t rowt = ((size_t)((q << 6) + t))*256 + n;
            const float4* pc0 = (const float4*)(g_pc + (size_t)row*HH + j2b);
            const float4* pc1 = (const float4*)(g_pc + (size_t)(BB*NN*HH) + (size_t)row*HH + j2b);
            const float4* gc  = (const float4*)(g_gx + rowt*G3 + 512 + j2b);
            const float4* pzp = (const float4*)(g_pzr + (size_t)row*512 + j2b);
            const float4* gzp = (const float4*)(g_gx + rowt*G3 + j2b);
            const float4* hp  = (const float4*)(g_h + (size_t)row*HH + j2b);
            float4* hw  = (float4*)(g_h + (size_t)row*HH + j2b);
            float4* hsw = (float4*)(g_hseq + rowt*HH + j2b);
            float4* shn = (float4*)(sh + n*20);
            #pragma unroll
            for (int w = 0; w < 4; w++){
                float4 c0 = __ldcg(pc0 + w);
                float4 c1 = __ldcg(pc1 + w);
                float4 gcv = __ldg(gc + w);
                float4 pz4 = __ldcg(pzp + w);
                float4 gz4 = __ldg(gzp + w);
                float4 h4  = __ldcg(hp + w);
                float4 hn;
                {
                    float z = sigmoidf_(pz4.x + gz4.x);
                    float c = tanhf(c0.x + c1.x + gcv.x);
                    hn.x = z*h4.x + (1.0f - z)*c;
                }
                {
                    float z = sigmoidf_(pz4.y + gz4.y);
                    float c = tanhf(c0.y + c1.y + gcv.y);
                    hn.y = z*h4.y + (1.0f - z)*c;
                }
                {
                    float z = sigmoidf_(pz4.z + gz4.z);
                    float c = tanhf(c0.z + c1.z + gcv.z);
                    hn.z = z*h4.z + (1.0f - z)*c;
                }
                {
                    float z = sigmoidf_(pz4.w + gz4.w);
                    float c = tanhf(c0.w + c1.w + gcv.w);
                    hn.w = z*h4.w + (1.0f - z)*c;
                }
                hw[w] = hn; hsw[w] = hn; shn[w] = hn;
            }
            __syncthreads();
            float* ax2 = writeAx ? (g_Axseq + ((size_t)((q << 6) + t))*256*HH + j2b) : (float*)0;
            spconv16(sh, g_Ah + (size_t)(q << 8)*HH + j2b, ax2);
        }
        gridbar(&gen);
    }
}

// ---------------- layer-1 gx GEMM: g_gx = g_Axseq @ Wx1 + b1 (128x128 tiles) ----------------
__global__ void __launch_bounds__(256, 2) gemm_gx1(const float* __restrict__ Wx1,
                                                   const float* __restrict__ b1){
    __shared__ __align__(16) float sA[2048];
    __shared__ __align__(16) float sB[4096];
    int tid = threadIdx.x;
    int r0 = blockIdx.y << 7;
    int j0 = blockIdx.x << 7;
    int lrow = tid >> 1, lk = (tid & 1) << 3;
    int bk = tid >> 4, bc = (tid & 15) << 3;
    int ty = tid >> 4, tx = tid & 15;

    u64 acc[4][8];
    #pragma unroll
    for (int i = 0; i < 4; i++)
        #pragma unroll
        for (int j = 0; j < 8; j++) acc[i][j] = 0ull;

    const float* ag = g_Axseq + (size_t)(r0 + lrow)*HH + lk;
    const float* bg = Wx1 + (size_t)bk*G3 + j0 + bc;

    float4 a0 = __ldg((const float4*)ag);
    float4 a1 = __ldg((const float4*)(ag + 4));
    float4 b0 = __ldg((const float4*)bg);
    float4 b1v = __ldg((const float4*)(bg + 4));

    for (int kc = 0; kc < 256; kc += 16){
        sA[(lk+0)*128 + lrow] = a0.x; sA[(lk+1)*128 + lrow] = a0.y;
        sA[(lk+2)*128 + lrow] = a0.z; sA[(lk+3)*128 + lrow] = a0.w;
        sA[(lk+4)*128 + lrow] = a1.x; sA[(lk+5)*128 + lrow] = a1.y;
        sA[(lk+6)*128 + lrow] = a1.z; sA[(lk+7)*128 + lrow] = a1.w;
        float* sbp = sB + bk*256 + bc*2;
        ((float4*)sbp)[0] = make_float4(b0.x, b0.x, b0.y, b0.y);
        ((float4*)sbp)[1] = make_float4(b0.z, b0.z, b0.w, b0.w);
        ((float4*)sbp)[2] = make_float4(b1v.x, b1v.x, b1v.y, b1v.y);
        ((float4*)sbp)[3] = make_float4(b1v.z, b1v.z, b1v.w, b1v.w);
        __syncthreads();
        if (kc + 16 < 256){
            a0 = __ldg((const float4*)(ag + kc + 16));
            a1 = __ldg((const float4*)(ag + kc + 20));
            const float* bg2 = bg + (size_t)(kc + 16)*G3;
            b0 = __ldg((const float4*)bg2);
            b1v = __ldg((const float4*)(bg2 + 4));
        }
        #pragma unroll
        for (int p = 0; p < 16; p++){
            F4U ta0, ta1;
            ta0.f = *(const float4*)(sA + p*128 + ty*8);
            ta1.f = *(const float4*)(sA + p*128 + ty*8 + 4);
            u64 ar[4] = { ta0.u[0], ta0.u[1], ta1.u[0], ta1.u[1] };
            F4U tb0, tb1, tb2, tb3;
            tb0.f = *(const float4*)(sB + p*256 + tx*16);
            tb1.f = *(const float4*)(sB + p*256 + tx*16 + 4);
            tb2.f = *(const float4*)(sB + p*256 + tx*16 + 8);
            tb3.f = *(const float4*)(sB + p*256 + tx*16 + 12);
            u64 bd[8] = { tb0.u[0], tb0.u[1], tb1.u[0], tb1.u[1],
                          tb2.u[0], tb2.u[1], tb3.u[0], tb3.u[1] };
            #pragma unroll
            for (int i = 0; i < 4; i++)
                #pragma unroll
                for (int j = 0; j < 8; j++) ffma2(acc[i][j], ar[i], bd[j]);
        }
        __syncthreads();
    }

    float bb[8];
    #pragma unroll
    for (int j = 0; j < 8; j++) bb[j] = b1[j0 + tx*8 + j];
    #pragma unroll
    for (int i = 0; i < 4; i++){
        float2 c[8];
        #pragma unroll
        for (int j = 0; j < 8; j++){
            c[j] = unpack2(acc[i][j]);
            c[j].x += bb[j]; c[j].y += bb[j];
        }
        float* rp = g_gx + (size_t)(r0 + ty*8 + 2*i)*G3 + j0 + tx*8;
        *(float4*)rp       = make_float4(c[0].x, c[1].x, c[2].x, c[3].x);
        *(float4*)(rp + 4) = make_float4(c[4].x, c[5].x, c[6].x, c[7].x);
        *(float4*)(rp + G3)     = make_float4(c[0].y, c[1].y, c[2].y, c[3].y);
        *(float4*)(rp + G3 + 4) = make_float4(c[4].y, c[5].y, c[6].y, c[7].y);
    }
}

// ---------------- output head ----------------
__global__ void out_head(const float* __restrict__ Wout, const float* __restrict__ bout,
                         float* __restrict__ out){
    __shared__ float sh[32*257];
    __shared__ float Ws[HH*DO];
    __shared__ float bs[DO];
    int r0 = blockIdx.x * 32;
    int tid = threadIdx.x;
    for (int i = tid; i < HH*DO; i += 256) Ws[i] = Wout[i];
    if (tid < DO) bs[tid] = bout[tid];
    const float4* H4 = (const float4*)g_hseq;
    for (int i = tid; i < 32*64; i += 256){
        int rr = i >> 6, c4 = i & 63;
        float4 v = H4[((size_t)(r0 + rr))*64 + c4];
        float* dst = &sh[rr*257 + c4*4];
        dst[0]=v.x; dst[1]=v.y; dst[2]=v.z; dst[3]=v.w;
    }
    __syncthreads();
    for (int oi = tid; oi < 32*DO; oi += 256){
        int rr = oi / DO, c = oi % DO;
        float a0 = bs[c], a1 = 0.0f;
        const float* sr = &sh[rr*257];
        for (int k = 0; k < HH; k += 2){
            a0 += sr[k]   * Ws[k*DO + c];
            a1 += sr[k+1] * Ws[(k+1)*DO + c];
        }
        out[(size_t)(r0 + rr)*DO + c] = a0 + a1;
    }
}

// ---------------- launch ----------------
extern "C" void kernel_launch(void* const* d_in, const int* in_sizes, int n_in,
                              void* d_out, int out_size) {
    const float* x2d  = (const float*)d_in[0];
    const float* mask = (const float*)d_in[1];
    const float* adj  = (const float*)d_in[2];
    const float* Wx0  = (const float*)d_in[3];
    const float* Wh0  = (const float*)d_in[4];
    const float* b0   = (const float*)d_in[5];
    const float* Wx1  = (const float*)d_in[6];
    const float* Wh1  = (const float*)d_in[7];
    const float* b1   = (const float*)d_in[8];
    const float* Wout = (const float*)d_in[9];
    const float* bout = (const float*)d_in[10];
    float* out = (float*)d_out;

    build_csr<<<1, 256>>>(adj);
    prep_gx0<<<BB*TT, 256>>>(x2d, mask, Wx0, b0);

    // layer 0 (also emits g_Axseq = A (x) hseq inline)
    gcgru_layer<<<NBLK, 256>>>(Wh0, 1);

    // layer-1 gx precompute
    gemm_gx1<<<dim3(6, (BB*TT*NN)/128), 256>>>(Wx1, b1);

    // layer 1
    gcgru_layer<<<NBLK, 256>>>(Wh1, 0);

    out_head<<<(BB*TT*NN)/32, 256>>>(Wout, bout, out);
}